// round 16
// baseline (speedup 1.0000x reference)
#include <cuda_runtime.h>
#include <cuda_fp16.h>
#include <stdint.h>
#include <math.h>

// LSTM cell: gates = x@W^T + pre_h@U^T via pure-fp16 mma.sync, fp32 accum.
// N = 128 = 32 units x 4 gates, gate-minor (n = u*4 + g).
// R16: PERSISTENT CTAs (296 = 2/SM), flat chunk counter keeps the 4-stage
// mbarrier ring warm across tiles; epilogue uses a dedicated 32KB buffer in
// two half-passes. Inner loop identical to R11 (best).

#define NBATCH 4096
#define NUNITS 2048
#define KD     2048
#define BM 128
#define NTILES 2048            // (2048/32 units) * (4096/128 rows)
#define NPERS 296              // persistent CTAs = 148 SMs * 2
#define NSTG 4
#define TILEB (128*64)         // 8192 B (128 rows x 32 fp16)
#define STAGEB (2*TILEB)       // Ah, Bh = 16384 B
#define EPIOFF (NSTG*STAGEB)   // 65536
#define EPIB   32768           // [4 warp-regions][64][32] fp32
#define SMEMB  (EPIOFF + EPIB + 128)

// -------- fp16 scratch --------
__device__ __align__(128) __half g_xh[(size_t)NBATCH*KD];
__device__ __align__(128) __half g_hh[(size_t)NBATCH*KD];
__device__ __align__(128) __half g_wh[(size_t)4*NUNITS*KD];
__device__ __align__(128) __half g_uh[(size_t)4*NUNITS*KD];

__device__ __forceinline__ uint32_t smem_u32(const void* p) {
    uint32_t a;
    asm("{ .reg .u64 t; cvta.to.shared.u64 t, %1; cvt.u32.u64 %0, t; }" : "=r"(a) : "l"(p));
    return a;
}
__device__ __forceinline__ void cp16(uint32_t dst, const void* src) {
    asm volatile("cp.async.cg.shared.global [%0], [%1], 16;" :: "r"(dst), "l"(src));
}
__device__ __forceinline__ void mbar_init(uint32_t m, uint32_t cnt) {
    asm volatile("mbarrier.init.shared.b64 [%0], %1;" :: "r"(m), "r"(cnt) : "memory");
}
__device__ __forceinline__ void mbar_arrive(uint32_t m) {
    asm volatile("mbarrier.arrive.shared.b64 _, [%0];" :: "r"(m) : "memory");
}
__device__ __forceinline__ void cp_arrive_noinc(uint32_t m) {
    asm volatile("cp.async.mbarrier.arrive.noinc.shared.b64 [%0];" :: "r"(m) : "memory");
}
__device__ __forceinline__ void mbar_wait(uint32_t m, uint32_t parity) {
    asm volatile(
        "{\n\t.reg .pred P;\n\t"
        "LAB%=:\n\t"
        "mbarrier.try_wait.parity.acquire.cta.shared::cta.b64 P, [%0], %1, 0x989680;\n\t"
        "@!P bra LAB%=;\n\t}"
        :: "r"(m), "r"(parity) : "memory");
}
__device__ __forceinline__ void ldsm4(uint32_t& r0, uint32_t& r1, uint32_t& r2, uint32_t& r3,
                                      uint32_t addr) {
    asm volatile("ldmatrix.sync.aligned.m8n8.x4.shared.b16 {%0,%1,%2,%3}, [%4];"
                 : "=r"(r0), "=r"(r1), "=r"(r2), "=r"(r3) : "r"(addr));
}
__device__ __forceinline__ void mma16816(float* d, const uint32_t* a, const uint32_t* b) {
    asm volatile(
        "mma.sync.aligned.m16n8k16.row.col.f32.f16.f16.f32 "
        "{%0,%1,%2,%3}, {%4,%5,%6,%7}, {%8,%9}, {%0,%1,%2,%3};"
        : "+f"(d[0]), "+f"(d[1]), "+f"(d[2]), "+f"(d[3])
        : "r"(a[0]), "r"(a[1]), "r"(a[2]), "r"(a[3]), "r"(b[0]), "r"(b[1]));
}

// load chunk with GLOBAL per-CTA index g: tile = bid + (g>>7)*NPERS, c = g&127
__device__ __forceinline__ void load_chunk_g(int g, int bid, uint32_t sbase, int tid) {
    const int c = g & 127;
    const int tile = bid + (g >> 7) * NPERS;
    const int bm = (tile >> 6) << 7;          // tile/64 * 128
    const int bu = (tile & 63) << 5;          // tile%64 * 32
    const uint32_t st = sbase + (uint32_t)(g & 3) * STAGEB;
    const int koff = (c & 63) * 32;
    const __half *Ah, *Bh;
    if (c < 64) { Ah = g_xh; Bh = g_wh; }
    else        { Ah = g_hh; Bh = g_uh; }
    #pragma unroll
    for (int i = 0; i < 2; ++i) {
        int e = i * 256 + tid;                 // 512 16B units per tile
        int r = e >> 2, ch = e & 3;
        uint32_t d = st + r * 64 + (((ch ^ ((r >> 1) & 3))) << 4);
        size_t ga = (size_t)(bm + r) * KD + koff + ch * 8;
        cp16(d, Ah + ga);
        int u = r >> 2, gg = r & 3;            // B row r: n = u*4 + g (gate-minor)
        size_t gb = ((size_t)(gg * NUNITS + bu + u)) * KD + koff + ch * 8;
        cp16(d + TILEB, Bh + gb);
    }
}

__global__ void __launch_bounds__(256, 2)
lstm_mma(const float* __restrict__ pre_c, float* __restrict__ out)
{
    extern __shared__ char smem[];
    const uint32_t sb = smem_u32(smem);
    const int tid = threadIdx.x, lane = tid & 31, wid = tid >> 5;
    const int bid = blockIdx.x;
    const int wm = (wid >> 2) * 64, wn = (wid & 3) * 32;

    const uint32_t mb = sb + EPIOFF + EPIB;    // mbarriers after epi buffer
    if (tid == 0) {
        #pragma unroll
        for (int s = 0; s < NSTG; ++s) { mbar_init(mb + 8 * s, 256); mbar_init(mb + 32 + 8 * s, 256); }
    }
    __syncthreads();

    const int ntiles = (NTILES - bid + NPERS - 1) / NPERS;   // 6 or 7
    const int total = ntiles * 128;

    float acc[4][4][4];
    #pragma unroll
    for (int i = 0; i < 4; ++i)
        #pragma unroll
        for (int j = 0; j < 4; ++j)
            #pragma unroll
            for (int k = 0; k < 4; ++k) acc[i][j][k] = 0.f;

    // prologue: chunks 0..2
    #pragma unroll
    for (int g0 = 0; g0 < 3; ++g0) {
        load_chunk_g(g0, bid, sb, tid);
        cp_arrive_noinc(mb + 8 * g0);
    }

    // A frag: row = wm + i*16 + (lane&15); logical 16B chunk ch = (lane>>4) + 2s
    const int rA = wm + (lane & 15);
    const uint32_t aBase = (uint32_t)rA * 64;
    const int selA = (rA >> 1) & 3;
    const int chA0 = lane >> 4;
    // B frag: row = wn + ((lane>>4)<<3) + (lane&7); ch = ((lane>>3)&1) + 2s
    const int rB = wn + (((lane >> 4) << 3) + (lane & 7));
    const uint32_t bBase = (uint32_t)rB * 64;
    const int selB = (rB >> 1) & 3;
    const int chB0 = (lane >> 3) & 1;

    const size_t CO = (size_t)NBATCH * NUNITS;
    float* S = (float*)(smem + EPIOFF);        // [4 warp-regions][64][32]

    #pragma unroll 1
    for (int g = 0; g < total; ++g) {
        const int s = g & 3;
        const uint32_t stv = sb + s * STAGEB;

        // ---- consume chunk g ----
        mbar_wait(mb + 8 * s, (uint32_t)((g >> 2) & 1));

        const uint32_t aH = stv + aBase;
        const uint32_t bH = stv + TILEB + bBase;
        #pragma unroll
        for (int sk = 0; sk < 2; ++sk) {
            const uint32_t offB = (uint32_t)(((chB0 + 2 * sk) ^ selB) << 4);
            const uint32_t offA = (uint32_t)(((chA0 + 2 * sk) ^ selA) << 4);
            uint32_t bh[4][2];
            #pragma unroll
            for (int jj = 0; jj < 2; ++jj) {
                uint32_t ad = bH + jj * 1024 + offB;
                ldsm4(bh[2*jj][0], bh[2*jj][1], bh[2*jj+1][0], bh[2*jj+1][1], ad);
            }
            #pragma unroll
            for (int i = 0; i < 4; ++i) {
                uint32_t ah[4];
                uint32_t ad = aH + i * 1024 + offA;
                ldsm4(ah[0], ah[1], ah[2], ah[3], ad);
                #pragma unroll
                for (int j = 0; j < 4; ++j)
                    mma16816(acc[i][j], ah, bh[j]);
            }
        }
        mbar_arrive(mb + 32 + 8 * s);          // stage s free (this thread)

        // ---- produce chunk g+3 (may belong to the next tile: ring stays warm) ----
        const int gp = g + 3;
        if (gp < total) {
            const int s2 = gp & 3;
            if (gp >= NSTG) mbar_wait(mb + 32 + 8 * s2, (uint32_t)(((gp >> 2) - 1) & 1));
            load_chunk_g(gp, bid, sb, tid);
            cp_arrive_noinc(mb + 8 * s2);
        }

        // ---- tile boundary: fused LSTM epilogue (two half-passes) ----
        if ((g & 127) == 127) {
            const int tile = bid + (g >> 7) * NPERS;
            const int bm = (tile >> 6) << 7;
            const int bu = (tile & 63) << 5;
            #pragma unroll
            for (int p = 0; p < 2; ++p) {
                // prefetch pre_c for this half
                float pcv[8];
                #pragma unroll
                for (int it = 0; it < 8; ++it) {
                    int idx = it * 256 + tid;
                    int ml = idx >> 5, u = idx & 31;
                    pcv[it] = pre_c[(size_t)(bm + p * 64 + ml) * NUNITS + bu + u];
                }
                if ((wid >> 2) == p) {         // stage this half's warps
                    const uint32_t base = (uint32_t)(wid & 3) * 2048;
                    #pragma unroll
                    for (int i = 0; i < 4; ++i)
                        #pragma unroll
                        for (int j = 0; j < 4; ++j) {
                            int r0 = i * 16 + (lane >> 2), c0 = j * 8 + (lane & 3) * 2;
                            *(float2*)&S[base + r0 * 32 + c0]       = make_float2(acc[i][j][0], acc[i][j][1]);
                            *(float2*)&S[base + (r0 + 8) * 32 + c0] = make_float2(acc[i][j][2], acc[i][j][3]);
                        }
                }
                __syncthreads();
                #pragma unroll
                for (int it = 0; it < 8; ++it) {
                    int idx = it * 256 + tid;
                    int ml = idx >> 5, u = idx & 31;
                    float4 gt = *(float4*)&S[(u >> 3) * 2048 + ml * 32 + (u & 7) * 4];
                    float itg = 1.f / (1.f + __expf(-gt.x));
                    float ftg = 1.f / (1.f + __expf(-gt.y));
                    float otg = 1.f / (1.f + __expf(-gt.z));
                    float ntg = tanhf(gt.w);
                    size_t o = (size_t)(bm + p * 64 + ml) * NUNITS + bu + u;
                    float cc = ftg * pcv[it] + itg * ntg;
                    float hh = otg * tanhf(cc);
                    out[o]      = hh;
                    out[CO + o] = cc;
                }
                __syncthreads();
            }
            // reset accumulators for next tile
            #pragma unroll
            for (int i = 0; i < 4; ++i)
                #pragma unroll
                for (int j = 0; j < 4; ++j)
                    #pragma unroll
                    for (int k = 0; k < 4; ++k) acc[i][j][k] = 0.f;
        }
    }
}

// -------- fp32 -> fp16 round, all tensors in one launch --------
__global__ void split_all(const float* __restrict__ x, const float* __restrict__ ph,
                          const float* __restrict__ W, const float* __restrict__ U)
{
    const int SEG = NBATCH * KD / 4;               // 2M float4 per x-like tensor
    int i = blockIdx.x * 256 + threadIdx.x;
    const float* s; __half* hi; int off;
    if (i < SEG)            { s = x;  hi = g_xh; off = i; }
    else if (i < 2 * SEG)   { s = ph; hi = g_hh; off = i - SEG; }
    else if (i < 4 * SEG)   { s = W;  hi = g_wh; off = i - 2 * SEG; }
    else                    { s = U;  hi = g_uh; off = i - 4 * SEG; }
    float4 v = reinterpret_cast<const float4*>(s)[off];
    __half2 h0 = __floats2half2_rn(v.x, v.y);
    __half2 h1 = __floats2half2_rn(v.z, v.w);
    uint32_t u0 = *reinterpret_cast<uint32_t*>(&h0);
    uint32_t u1 = *reinterpret_cast<uint32_t*>(&h1);
    reinterpret_cast<uint2*>(hi)[off] = make_uint2(u0, u1);
}

extern "C" void kernel_launch(void* const* d_in, const int* in_sizes, int n_in,
                              void* d_out, int out_size)
{
    const float* pre_layer = (const float*)d_in[0];  // (2, 4096, 2048)
    const float* x         = (const float*)d_in[1];  // (4096, 2048)
    const float* W         = (const float*)d_in[2];  // (4, 2048, 2048)
    const float* U         = (const float*)d_in[3];  // (4, 2048, 2048)
    float* out             = (float*)d_out;

    const int SEG = NBATCH * KD / 4;                 // 2M
    const int total = 6 * SEG;                       // x(1) + h(1) + W(2) + U(2)
    split_all<<<total / 256, 256>>>(x, pre_layer, W, U);

    cudaFuncSetAttribute(lstm_mma, cudaFuncAttributeMaxDynamicSharedMemorySize, SMEMB);
    const float* pre_c = pre_layer + (size_t)NBATCH * NUNITS;
    lstm_mma<<<NPERS, 256, SMEMB>>>(pre_c, out);
}

// round 17
// speedup vs baseline: 1.1626x; 1.1626x over previous
#include <cuda_runtime.h>
#include <cuda_fp16.h>
#include <stdint.h>
#include <math.h>

// LSTM cell: gates = x@W^T + pre_h@U^T via pure-fp16 mma.sync, fp32 accum.
// N = 128 = 32 units x 4 gates, gate-minor (n = u*4 + g).
// R17 = R11 (best: 653us) + per-warp elected free-barrier arrives (count 8
// instead of 256) to cut smem-atomic serialization per chunk.

#define NBATCH 4096
#define NUNITS 2048
#define KD     2048
#define BM 128
#define BK 32
#define NCH 128                // 2 phases * (2048/32)
#define NSTG 4
#define TILEB (128*64)         // 8192 B (128 rows x 32 fp16)
#define STAGEB (2*TILEB)       // Ah, Bh = 16384 B
#define SMEMB (NSTG*STAGEB + 64)

// -------- fp16 scratch --------
__device__ __align__(128) __half g_xh[(size_t)NBATCH*KD];
__device__ __align__(128) __half g_hh[(size_t)NBATCH*KD];
__device__ __align__(128) __half g_wh[(size_t)4*NUNITS*KD];
__device__ __align__(128) __half g_uh[(size_t)4*NUNITS*KD];

__device__ __forceinline__ uint32_t smem_u32(const void* p) {
    uint32_t a;
    asm("{ .reg .u64 t; cvta.to.shared.u64 t, %1; cvt.u32.u64 %0, t; }" : "=r"(a) : "l"(p));
    return a;
}
__device__ __forceinline__ void cp16(uint32_t dst, const void* src) {
    asm volatile("cp.async.cg.shared.global [%0], [%1], 16;" :: "r"(dst), "l"(src));
}
__device__ __forceinline__ void mbar_init(uint32_t m, uint32_t cnt) {
    asm volatile("mbarrier.init.shared.b64 [%0], %1;" :: "r"(m), "r"(cnt) : "memory");
}
__device__ __forceinline__ void mbar_arrive(uint32_t m) {
    asm volatile("mbarrier.arrive.shared.b64 _, [%0];" :: "r"(m) : "memory");
}
__device__ __forceinline__ void cp_arrive_noinc(uint32_t m) {
    asm volatile("cp.async.mbarrier.arrive.noinc.shared.b64 [%0];" :: "r"(m) : "memory");
}
__device__ __forceinline__ void mbar_wait(uint32_t m, uint32_t parity) {
    asm volatile(
        "{\n\t.reg .pred P;\n\t"
        "LAB%=:\n\t"
        "mbarrier.try_wait.parity.acquire.cta.shared::cta.b64 P, [%0], %1, 0x989680;\n\t"
        "@!P bra LAB%=;\n\t}"
        :: "r"(m), "r"(parity) : "memory");
}
__device__ __forceinline__ void ldsm4(uint32_t& r0, uint32_t& r1, uint32_t& r2, uint32_t& r3,
                                      uint32_t addr) {
    asm volatile("ldmatrix.sync.aligned.m8n8.x4.shared.b16 {%0,%1,%2,%3}, [%4];"
                 : "=r"(r0), "=r"(r1), "=r"(r2), "=r"(r3) : "r"(addr));
}
__device__ __forceinline__ void mma16816(float* d, const uint32_t* a, const uint32_t* b) {
    asm volatile(
        "mma.sync.aligned.m16n8k16.row.col.f32.f16.f16.f32 "
        "{%0,%1,%2,%3}, {%4,%5,%6,%7}, {%8,%9}, {%0,%1,%2,%3};"
        : "+f"(d[0]), "+f"(d[1]), "+f"(d[2]), "+f"(d[3])
        : "r"(a[0]), "r"(a[1]), "r"(a[2]), "r"(a[3]), "r"(b[0]), "r"(b[1]));
}

// one chunk: Ah, Bh tiles (128 rows x 32 fp16 each); 4 cp16/thread
__device__ __forceinline__ void load_chunk(int c, uint32_t st, int bm, int bu, int tid) {
    const int koff = (c & 63) * BK;
    const __half *Ah, *Bh;
    if (c < 64) { Ah = g_xh; Bh = g_wh; }
    else        { Ah = g_hh; Bh = g_uh; }
    #pragma unroll
    for (int i = 0; i < 2; ++i) {
        int e = i * 256 + tid;                 // 512 16B units per tile
        int r = e >> 2, ch = e & 3;
        uint32_t d = st + r * 64 + (((ch ^ ((r >> 1) & 3))) << 4);
        size_t ga = (size_t)(bm + r) * KD + koff + ch * 8;
        cp16(d, Ah + ga);
        int u = r >> 2, g = r & 3;             // B row r: n = u*4 + g (gate-minor)
        size_t gb = ((size_t)(g * NUNITS + bu + u)) * KD + koff + ch * 8;
        cp16(d + TILEB, Bh + gb);
    }
}

__global__ void __launch_bounds__(256, 2)
lstm_mma(const float* __restrict__ pre_c, float* __restrict__ out)
{
    extern __shared__ char smem[];
    const uint32_t sb = smem_u32(smem);
    const int tid = threadIdx.x, lane = tid & 31, wid = tid >> 5;
    const int bm = blockIdx.y * BM, bu = blockIdx.x * 32;
    const int wm = (wid >> 2) * 64, wn = (wid & 3) * 32;

    const uint32_t mb = sb + NSTG * STAGEB;    // mbarrier block
    // full[s] = mb + 8*s (count 256, cp.async completions)
    // free[s] = mb + 32 + 8*s (count 8, one elected arrive per warp)
    if (tid == 0) {
        #pragma unroll
        for (int s = 0; s < NSTG; ++s) { mbar_init(mb + 8 * s, 256); mbar_init(mb + 32 + 8 * s, 8); }
    }
    __syncthreads();

    float acc[4][4][4];
    #pragma unroll
    for (int i = 0; i < 4; ++i)
        #pragma unroll
        for (int j = 0; j < 4; ++j)
            #pragma unroll
            for (int k = 0; k < 4; ++k) acc[i][j][k] = 0.f;

    // prologue: load chunks 0..2, arm full[0..2]
    #pragma unroll
    for (int c0 = 0; c0 < 3; ++c0) {
        load_chunk(c0, sb + c0 * STAGEB, bm, bu, tid);
        cp_arrive_noinc(mb + 8 * c0);
    }

    // A frag: row = wm + i*16 + (lane&15); logical 16B chunk ch = (lane>>4) + 2s
    const int rA = wm + (lane & 15);
    const uint32_t aBase = (uint32_t)rA * 64;
    const int selA = (rA >> 1) & 3;
    const int chA0 = lane >> 4;
    // B frag: row = wn + ((lane>>4)<<3) + (lane&7); ch = ((lane>>3)&1) + 2s
    const int rB = wn + (((lane >> 4) << 3) + (lane & 7));
    const uint32_t bBase = (uint32_t)rB * 64;
    const int selB = (rB >> 1) & 3;
    const int chB0 = (lane >> 3) & 1;

    #pragma unroll 1
    for (int c = 0; c < NCH; ++c) {
        const int s = c & 3;
        const uint32_t stv = sb + s * STAGEB;

        // ---- consume chunk c ----
        mbar_wait(mb + 8 * s, (uint32_t)((c >> 2) & 1));

        const uint32_t aH = stv + aBase;
        const uint32_t bH = stv + TILEB + bBase;
        #pragma unroll
        for (int sk = 0; sk < 2; ++sk) {
            const uint32_t offB = (uint32_t)(((chB0 + 2 * sk) ^ selB) << 4);
            const uint32_t offA = (uint32_t)(((chA0 + 2 * sk) ^ selA) << 4);
            uint32_t bh[4][2];
            #pragma unroll
            for (int jj = 0; jj < 2; ++jj) {
                uint32_t ad = bH + jj * 1024 + offB;
                ldsm4(bh[2*jj][0], bh[2*jj][1], bh[2*jj+1][0], bh[2*jj+1][1], ad);
            }
            #pragma unroll
            for (int i = 0; i < 4; ++i) {
                uint32_t ah[4];
                uint32_t ad = aH + i * 1024 + offA;
                ldsm4(ah[0], ah[1], ah[2], ah[3], ad);
                #pragma unroll
                for (int j = 0; j < 4; ++j)
                    mma16816(acc[i][j], ah, bh[j]);
            }
        }
        if (lane == 0) mbar_arrive(mb + 32 + 8 * s);   // per-warp free arrive

        // ---- produce chunk c+3 ----
        const int cp = c + 3;
        if (cp < NCH) {
            const int s2 = cp & 3;
            if (cp >= NSTG) mbar_wait(mb + 32 + 8 * s2, (uint32_t)(((cp >> 2) - 1) & 1));
            load_chunk(cp, sb + s2 * STAGEB, bm, bu, tid);
            cp_arrive_noinc(mb + 8 * s2);
        }
    }
    __syncthreads();   // all warps done; smem reusable

    // ---------------- fused LSTM epilogue ----------------
    const size_t CO = (size_t)NBATCH * NUNITS;
    float pcv[16];
    #pragma unroll
    for (int i = 0; i < 16; ++i) {
        int idx = i * 256 + tid;
        int m = idx >> 5, u = idx & 31;
        pcv[i] = pre_c[(size_t)(bm + m) * NUNITS + bu + u];
    }
    float* S = (float*)smem;                 // [8 warps][64 m][32 n-local]
    const uint32_t base = wid * 2048;
    #pragma unroll
    for (int i = 0; i < 4; ++i)
        #pragma unroll
        for (int j = 0; j < 4; ++j) {
            int r0 = i * 16 + (lane >> 2), c0 = j * 8 + (lane & 3) * 2;
            *(float2*)&S[base + r0 * 32 + c0]       = make_float2(acc[i][j][0], acc[i][j][1]);
            *(float2*)&S[base + (r0 + 8) * 32 + c0] = make_float2(acc[i][j][2], acc[i][j][3]);
        }
    __syncthreads();

    #pragma unroll
    for (int i = 0; i < 16; ++i) {
        int idx = i * 256 + tid;
        int m = idx >> 5, u = idx & 31;
        int wreg = (m >> 6) * 4 + (u >> 3);
        float4 gt = *(float4*)&S[wreg * 2048 + (m & 63) * 32 + (u & 7) * 4];
        float it = 1.f / (1.f + __expf(-gt.x));
        float ft = 1.f / (1.f + __expf(-gt.y));
        float ot = 1.f / (1.f + __expf(-gt.z));
        float nt = tanhf(gt.w);
        size_t o = (size_t)(bm + m) * NUNITS + bu + u;
        float cc = ft * pcv[i] + it * nt;
        float hh = ot * tanhf(cc);
        out[o]      = hh;
        out[CO + o] = cc;
    }
}

// -------- fp32 -> fp16 round, all tensors in one launch --------
__global__ void split_all(const float* __restrict__ x, const float* __restrict__ ph,
                          const float* __restrict__ W, const float* __restrict__ U)
{
    const int SEG = NBATCH * KD / 4;               // 2M float4 per x-like tensor
    int i = blockIdx.x * 256 + threadIdx.x;
    const float* s; __half* hi; int off;
    if (i < SEG)            { s = x;  hi = g_xh; off = i; }
    else if (i < 2 * SEG)   { s = ph; hi = g_hh; off = i - SEG; }
    else if (i < 4 * SEG)   { s = W;  hi = g_wh; off = i - 2 * SEG; }
    else                    { s = U;  hi = g_uh; off = i - 4 * SEG; }
    float4 v = reinterpret_cast<const float4*>(s)[off];
    __half2 h0 = __floats2half2_rn(v.x, v.y);
    __half2 h1 = __floats2half2_rn(v.z, v.w);
    uint32_t u0 = *reinterpret_cast<uint32_t*>(&h0);
    uint32_t u1 = *reinterpret_cast<uint32_t*>(&h1);
    reinterpret_cast<uint2*>(hi)[off] = make_uint2(u0, u1);
}

extern "C" void kernel_launch(void* const* d_in, const int* in_sizes, int n_in,
                              void* d_out, int out_size)
{
    const float* pre_layer = (const float*)d_in[0];  // (2, 4096, 2048)
    const float* x         = (const float*)d_in[1];  // (4096, 2048)
    const float* W         = (const float*)d_in[2];  // (4, 2048, 2048)
    const float* U         = (const float*)d_in[3];  // (4, 2048, 2048)
    float* out             = (float*)d_out;

    const int SEG = NBATCH * KD / 4;                 // 2M
    const int total = 6 * SEG;                       // x(1) + h(1) + W(2) + U(2)
    split_all<<<total / 256, 256>>>(x, pre_layer, W, U);

    cudaFuncSetAttribute(lstm_mma, cudaFuncAttributeMaxDynamicSharedMemorySize, SMEMB);
    const float* pre_c = pre_layer + (size_t)NBATCH * NUNITS;
    lstm_mma<<<dim3(NUNITS / 32, NBATCH / BM), 256, SMEMB>>>(pre_c, out);
}